// round 7
// baseline (speedup 1.0000x reference)
#include <cuda_runtime.h>
#include <cuda_fp16.h>
#include <cstdint>

// MlaNer1: B=64, L=512, H2=1536, T=64 -> GEMM M=32768, N=64, K=1536
#define K_DIM   1536
#define N_DIM   64
#define BM      256              // CTA M-tile (8 warps x 32 rows)
#define BK      16               // K per chunk = one k16 MMA step
#define NCHUNK  (K_DIM / BK)     // 96
#define NTHREADS 256
#define MAX_BLOCKS 512
#define STRIDE_U 12              // u32 per row (8 data + 4 pad); 48B row stride

// W prescale 2^10 (exact); logits descaled in epilogue
#define WSCALE     1024.0f
#define INV_WSCALE (1.0f / 1024.0f)

// smem u32-offsets
#define U_BIAS  0
#define U_BUF   64
#define U_XHI   0
#define U_XLO   (BM * STRIDE_U)                          // 3072
#define U_WHI   (2 * BM * STRIDE_U)                      // 6144
#define U_WLO   (2 * BM * STRIDE_U + N_DIM * STRIDE_U)   // 6912
#define U_BUFSZ (2 * BM * STRIDE_U + 2 * N_DIM * STRIDE_U) // 7680
#define SMEM_U32 (U_BUF + 2 * U_BUFSZ)                   // 15424
#define SMEM_BYTES (SMEM_U32 * 4)                        // 61696

__device__ float g_partLoss[MAX_BLOCKS];
__device__ int   g_partRight[MAX_BLOCKS];
__device__ int   g_partCount[MAX_BLOCKS];
// W transposed to [N,K], prescaled, fp16-split, packed half2
__device__ __align__(16) uint32_t g_Wp_hi[N_DIM * K_DIM / 2];
__device__ __align__(16) uint32_t g_Wp_lo[N_DIM * K_DIM / 2];

static __device__ __forceinline__ uint32_t smem_u32(const void* p) {
    uint32_t a;
    asm("{ .reg .u64 t; cvta.to.shared.u64 t, %1; cvt.u32.u64 %0, t; }" : "=r"(a) : "l"(p));
    return a;
}
// f32-acc fp16 MMA (hh term)
static __device__ __forceinline__ void mma_f32acc(float* c, const uint32_t* a,
                                                  const uint32_t* b) {
    asm volatile("mma.sync.aligned.m16n8k16.row.col.f32.f16.f16.f32 "
        "{%0,%1,%2,%3}, {%4,%5,%6,%7}, {%8,%9}, {%0,%1,%2,%3};"
        : "+f"(c[0]), "+f"(c[1]), "+f"(c[2]), "+f"(c[3])
        : "r"(a[0]), "r"(a[1]), "r"(a[2]), "r"(a[3]), "r"(b[0]), "r"(b[1]));
}
// f16-acc fp16 MMA (correction terms; values tiny -> fp16 acc safe)
static __device__ __forceinline__ void mma_f16acc(uint32_t* c, const uint32_t* a,
                                                  const uint32_t* b) {
    asm volatile("mma.sync.aligned.m16n8k16.row.col.f16.f16.f16.f16 "
        "{%0,%1}, {%2,%3,%4,%5}, {%6,%7}, {%0,%1};"
        : "+r"(c[0]), "+r"(c[1])
        : "r"(a[0]), "r"(a[1]), "r"(a[2]), "r"(a[3]), "r"(b[0]), "r"(b[1]));
}
#define LDMX4(r0, r1, r2, r3, addr) \
    asm volatile("ldmatrix.sync.aligned.m8n8.x4.shared.b16 {%0,%1,%2,%3}, [%4];" \
        : "=r"(r0), "=r"(r1), "=r"(r2), "=r"(r3) : "r"(addr))

static __device__ __forceinline__ void split2(float f0, float f1,
                                              uint32_t& hi, uint32_t& lo) {
    __half2 h = __floats2half2_rn(f0, f1);
    float2  fh = __half22float2(h);
    __half2 l = __floats2half2_rn(f0 - fh.x, f1 - fh.y);
    hi = *reinterpret_cast<uint32_t*>(&h);
    lo = *reinterpret_cast<uint32_t*>(&l);
}

// ---- pre-kernel: transpose W [K,N] -> [N,K], prescale, fp16-split, pack ----
__global__ void split_w_kernel(const float* __restrict__ W) {
    int idx = blockIdx.x * blockDim.x + threadIdx.x;   // over N*K/2
    if (idx < N_DIM * K_DIM / 2) {
        int n  = idx / (K_DIM / 2);
        int kk = idx - n * (K_DIM / 2);
        float w0 = W[(size_t)(2 * kk)     * N_DIM + n] * WSCALE;
        float w1 = W[(size_t)(2 * kk + 1) * N_DIM + n] * WSCALE;
        uint32_t hi, lo;
        split2(w0, w1, hi, lo);
        g_Wp_hi[idx] = hi;
        g_Wp_lo[idx] = lo;
    }
}

// ---- fused 3-pass fp16-split mma GEMM + softmax-stats + loss/acc ----
__global__ __launch_bounds__(NTHREADS, 1)
void fused_kernel(const float* __restrict__ x,
                  const float* __restrict__ bias,
                  const int* __restrict__ tags,
                  const float* __restrict__ t2s,
                  const int* __restrict__ tptr,
                  int M)
{
    extern __shared__ uint32_t smem[];
    float* smf = (float*)smem;
    const int tid  = threadIdx.x;
    const int w    = tid >> 5;
    const int lane = tid & 31;
    const int g    = lane >> 2;   // 0..7
    const int t    = lane & 3;    // 0..3
    const int m0   = blockIdx.x * BM;

    if (tid < N_DIM) smf[U_BIAS + tid] = bias[tid];

    const uint32_t smb = smem_u32(smem);
    const uint32_t buf_base[2] = { smb + U_BUF * 4u, smb + (U_BUF + U_BUFSZ) * 4u };

    // ldmatrix per-lane byte offsets (relative to buffer base)
    // A (per mt): lanes 0-7 rows 0-7 k0-7; 8-15 rows 8-15 k0-7; 16-23 rows 0-7 +16B; 24-31 rows 8-15 +16B
    uint32_t a_off[2];
    {
        const int r    = lane & 7;
        const int rb   = (lane >> 3) & 1;     // row-block 0/1
        const int kb   = (lane >> 4) & 1;     // k-half
        #pragma unroll
        for (int mt = 0; mt < 2; mt++) {
            int row = 32 * w + 16 * mt + 8 * rb + r;
            a_off[mt] = (U_XHI + row * STRIDE_U) * 4u + kb * 16u;
        }
    }
    // B (per nt-pair p): tiles (nt=2p k0),(nt=2p k8),(nt=2p+1 k0),(nt=2p+1 k8)
    uint32_t b_off[4];
    {
        const int r  = lane & 7;
        const int tl = lane >> 3;             // 0..3
        const int nb = tl >> 1;               // n sub-block
        const int kb = tl & 1;
        #pragma unroll
        for (int p = 0; p < 4; p++) {
            int nrow = 16 * p + 8 * nb + r;
            b_off[p] = (U_WHI + nrow * STRIDE_U) * 4u + kb * 16u;
        }
    }
    const uint32_t XLO_D = (U_XLO - U_XHI) * 4u;
    const uint32_t WLO_D = (U_WLO - U_WHI) * 4u;

    // staging: thread tid stages x row tid; W: n = tid>>2, u32 pair (tid&3)*2
    int arow = m0 + tid; if (arow >= M) arow = M - 1;
    const float* xrow = x + (size_t)arow * K_DIM;
    const int wn = tid >> 2;
    const int wq = (tid & 3) * 2;
    const uint32_t* whp = g_Wp_hi + (size_t)wn * (K_DIM / 2) + wq;
    const uint32_t* wlp = g_Wp_lo + (size_t)wn * (K_DIM / 2) + wq;

    float    accF[2][8][4];     // hh (f32 acc)
    uint32_t accH[2][8][2];     // hl + lh (f16 acc, tiny values)
    #pragma unroll
    for (int mt = 0; mt < 2; mt++)
        #pragma unroll
        for (int nt = 0; nt < 8; nt++) {
            #pragma unroll
            for (int q = 0; q < 4; q++) accF[mt][nt][q] = 0.f;
            accH[mt][nt][0] = 0u; accH[mt][nt][1] = 0u;
        }

    // prologue LDG chunk 0
    float4 xa[4]; uint2 wh, wl;
    #pragma unroll
    for (int q = 0; q < 4; q++) xa[q] = *(const float4*)(xrow + 4 * q);
    wh = *(const uint2*)whp;
    wl = *(const uint2*)wlp;

    int buf = 0;
    for (int c = 0; c < NCHUNK; ++c) {
        uint32_t* S = smem + U_BUF + buf * U_BUFSZ;

        // ---- stage: fp16-split x; store pre-split W ----
        {
            uint32_t xh[8], xl[8];
            #pragma unroll
            for (int q = 0; q < 4; q++) {
                split2(xa[q].x, xa[q].y, xh[2 * q],     xl[2 * q]);
                split2(xa[q].z, xa[q].w, xh[2 * q + 1], xl[2 * q + 1]);
            }
            uint4* ph = (uint4*)(S + U_XHI + tid * STRIDE_U);
            uint4* pl = (uint4*)(S + U_XLO + tid * STRIDE_U);
            ph[0] = make_uint4(xh[0], xh[1], xh[2], xh[3]);
            ph[1] = make_uint4(xh[4], xh[5], xh[6], xh[7]);
            pl[0] = make_uint4(xl[0], xl[1], xl[2], xl[3]);
            pl[1] = make_uint4(xl[4], xl[5], xl[6], xl[7]);
            *(uint2*)(S + U_WHI + wn * STRIDE_U + wq) = wh;
            *(uint2*)(S + U_WLO + wn * STRIDE_U + wq) = wl;
        }

        __syncthreads();

        // prefetch next chunk
        if (c + 1 < NCHUNK) {
            const float* xp = xrow + (c + 1) * BK;
            #pragma unroll
            for (int q = 0; q < 4; q++) xa[q] = *(const float4*)(xp + 4 * q);
            wh = *(const uint2*)(whp + (c + 1) * 8);
            wl = *(const uint2*)(wlp + (c + 1) * 8);
        }

        // ---- fragment loads via ldmatrix.x4 ----
        const uint32_t base = buf_base[buf];
        uint32_t ah[2][4], al[2][4], bh[8][2], bl[8][2];
        #pragma unroll
        for (int mt = 0; mt < 2; mt++) {
            LDMX4(ah[mt][0], ah[mt][1], ah[mt][2], ah[mt][3], base + a_off[mt]);
            LDMX4(al[mt][0], al[mt][1], al[mt][2], al[mt][3], base + a_off[mt] + XLO_D);
        }
        #pragma unroll
        for (int p = 0; p < 4; p++) {
            LDMX4(bh[2*p][0], bh[2*p][1], bh[2*p+1][0], bh[2*p+1][1], base + b_off[p]);
            LDMX4(bl[2*p][0], bl[2*p][1], bl[2*p+1][0], bl[2*p+1][1], base + b_off[p] + WLO_D);
        }

        // ---- MMAs: 16 hh (f32 acc) + 32 corrections (f16 acc) ----
        #pragma unroll
        for (int nt = 0; nt < 8; nt++)
            #pragma unroll
            for (int mt = 0; mt < 2; mt++)
                mma_f32acc(accF[mt][nt], ah[mt], bh[nt]);       // hi*hi
        #pragma unroll
        for (int nt = 0; nt < 8; nt++)
            #pragma unroll
            for (int mt = 0; mt < 2; mt++)
                mma_f16acc(accH[mt][nt], ah[mt], bl[nt]);       // hi*lo
        #pragma unroll
        for (int nt = 0; nt < 8; nt++)
            #pragma unroll
            for (int mt = 0; mt < 2; mt++)
                mma_f16acc(accH[mt][nt], al[mt], bh[nt]);       // lo*hi

        buf ^= 1;
    }

    // ---- epilogue: quad owns rows; lane holds cols 8*nt + 2*t + j ----
    const int   tval = *tptr;
    const float E1   = 2.718281828459045f;
    float myLoss = 0.f;
    int myRight = 0, myCount = 0;

    #pragma unroll
    for (int mt = 0; mt < 2; mt++) {
        #pragma unroll
        for (int half = 0; half < 2; half++) {
            const int grow = m0 + 32 * w + 16 * mt + 8 * half + g;
            float v[16];
            float lmax = -1e30f, lsum = 0.f;
            int lidx = 0;
            #pragma unroll
            for (int nt = 0; nt < 8; nt++) {
                __half2 hc = *reinterpret_cast<__half2*>(&accH[mt][nt][half]);
                float2  cf = __half22float2(hc);
                #pragma unroll
                for (int j = 0; j < 2; j++) {
                    const int col = 8 * nt + 2 * t + j;
                    float corr = j ? cf.y : cf.x;
                    float f = (accF[mt][nt][2 * half + j] + corr) * INV_WSCALE
                              + smf[U_BIAS + col];
                    v[2 * nt + j] = f;
                    lsum += f;
                    if (f > lmax) { lmax = f; lidx = col; }
                }
            }
            #pragma unroll
            for (int o = 1; o < 4; o <<= 1) {
                float om = __shfl_xor_sync(0xffffffffu, lmax, o, 4);
                int   oi = __shfl_xor_sync(0xffffffffu, lidx, o, 4);
                if (om > lmax || (om == lmax && oi < lidx)) { lmax = om; lidx = oi; }
            }
            float z = 0.f;
            #pragma unroll
            for (int q = 0; q < 16; q++) z += __expf(v[q] - lmax);
            #pragma unroll
            for (int o = 1; o < 4; o <<= 1) {
                z    += __shfl_xor_sync(0xffffffffu, z,    o, 4);
                lsum += __shfl_xor_sync(0xffffffffu, lsum, o, 4);
            }

            if (grow < M) {
                const int tg = tags[grow];
                if (((tg >> 1) & 3) == t) {
                    float ltag = v[0];
                    #pragma unroll
                    for (int nt = 0; nt < 8; nt++)
                        #pragma unroll
                        for (int j = 0; j < 2; j++)
                            if (tg == 8 * nt + 2 * t + j) ltag = v[2 * nt + j];

                    float logZ   = __logf(z);
                    float lp_tag = ltag - lmax - logZ;
                    float S_log  = lsum - 64.f * (lmax + logZ);
                    float s  = t2s[tg];
                    float sc = powf(s, (float)tval);
                    float es = __expf(sc);
                    float Zy = 63.f * E1 + es;
                    float y_non = E1 / Zy;
                    float y_hot = es / Zy;
                    myLoss -= y_non * S_log + (y_hot - y_non) * lp_tag;
                    if (tg < N_DIM - 3) { myCount++; if (lidx == tg) myRight++; }
                }
            }
        }
    }

    // ---- deterministic block tree-reduction ----
    __syncthreads();
    float* rl = smf + U_BUF;
    int*   rr = (int*)(smem + U_BUF + NTHREADS);
    int*   rc = (int*)(smem + U_BUF + 2 * NTHREADS);
    rl[tid] = myLoss; rr[tid] = myRight; rc[tid] = myCount;
    __syncthreads();
    #pragma unroll
    for (int s2 = NTHREADS / 2; s2 > 0; s2 >>= 1) {
        if (tid < s2) { rl[tid] += rl[tid + s2]; rr[tid] += rr[tid + s2]; rc[tid] += rc[tid + s2]; }
        __syncthreads();
    }
    if (tid == 0) {
        g_partLoss[blockIdx.x]  = rl[0];
        g_partRight[blockIdx.x] = rr[0];
        g_partCount[blockIdx.x] = rc[0];
    }
}

__global__ void finalize_kernel(float* __restrict__ out, int nb)
{
    __shared__ float sl[256];
    __shared__ int   sr[256];
    __shared__ int   sc[256];
    const int t = threadIdx.x;
    float L = 0.f; int R = 0, C = 0;
    for (int i = t; i < nb; i += 256) {
        L += g_partLoss[i]; R += g_partRight[i]; C += g_partCount[i];
    }
    sl[t] = L; sr[t] = R; sc[t] = C;
    __syncthreads();
    for (int s = 128; s > 0; s >>= 1) {
        if (t < s) { sl[t] += sl[t + s]; sr[t] += sr[t + s]; sc[t] += sc[t + s]; }
        __syncthreads();
    }
    if (t == 0) {
        out[0] = sl[0];
        out[1] = (float)sr[0] / (float)sc[0];
    }
}

extern "C" void kernel_launch(void* const* d_in, const int* in_sizes, int n_in,
                              void* d_out, int out_size)
{
    // metadata order: x, W, b, tags, attention_mask, tag_to_score, t
    const float* x    = (const float*)d_in[0];
    const float* W    = (const float*)d_in[1];
    const float* b    = (const float*)d_in[2];
    const int*   tags = (const int*)d_in[3];
    // d_in[4] attention_mask: uniform additive shift over softmax axis -> no-op
    const float* t2s  = (const float*)d_in[5];
    const int*   tptr = (const int*)d_in[6];

    const int M = in_sizes[3];                   // 32768
    int nblocks = (M + BM - 1) / BM;             // 128
    if (nblocks > MAX_BLOCKS) nblocks = MAX_BLOCKS;

    cudaFuncSetAttribute(fused_kernel, cudaFuncAttributeMaxDynamicSharedMemorySize, SMEM_BYTES);

    split_w_kernel<<<(N_DIM * K_DIM / 2 + 255) / 256, 256>>>(W);
    fused_kernel<<<nblocks, NTHREADS, SMEM_BYTES>>>(x, b, tags, t2s, tptr, M);
    finalize_kernel<<<1, 256>>>((float*)d_out, nblocks);
}

// round 8
// speedup vs baseline: 1.1456x; 1.1456x over previous
#include <cuda_runtime.h>
#include <cuda_fp16.h>
#include <cstdint>

// MlaNer1: B=64, L=512, H2=1536, T=64 -> GEMM M=32768, N=64, K=1536
#define K_DIM   1536
#define N_DIM   64
#define BM      128              // CTA M-tile (4 warps x 32 rows)
#define BK      32               // K per chunk = two k16 MMA steps
#define NCHUNK  (K_DIM / BK)     // 48
#define NTHREADS 128
#define MAX_BLOCKS 512
#define STRIDE_U 20              // u32 per row (16 data + 4 pad); 80B stride

// W prescale 2^10 (exact); logits descaled in epilogue
#define WSCALE     1024.0f
#define INV_WSCALE (1.0f / 1024.0f)

// smem u32-offsets
#define U_BIAS  0
#define U_BUF   64
#define U_XHI   0
#define U_XLO   (BM * STRIDE_U)                          // 2560
#define U_WHI   (2 * BM * STRIDE_U)                      // 5120
#define U_WLO   (2 * BM * STRIDE_U + N_DIM * STRIDE_U)   // 6400
#define U_BUFSZ (2 * BM * STRIDE_U + 2 * N_DIM * STRIDE_U) // 7680
#define SMEM_U32 (U_BUF + 2 * U_BUFSZ)                   // 15424
#define SMEM_BYTES (SMEM_U32 * 4)                        // 61696 (fits 2 CTA/SM)

__device__ float g_partLoss[MAX_BLOCKS];
__device__ int   g_partRight[MAX_BLOCKS];
__device__ int   g_partCount[MAX_BLOCKS];
// W transposed to [N,K], prescaled, fp16-split, packed half2
__device__ __align__(16) uint32_t g_Wp_hi[N_DIM * K_DIM / 2];
__device__ __align__(16) uint32_t g_Wp_lo[N_DIM * K_DIM / 2];

static __device__ __forceinline__ uint32_t smem_u32(const void* p) {
    uint32_t a;
    asm("{ .reg .u64 t; cvta.to.shared.u64 t, %1; cvt.u32.u64 %0, t; }" : "=r"(a) : "l"(p));
    return a;
}
static __device__ __forceinline__ void mma_f32acc(float* c, const uint32_t* a,
                                                  const uint32_t* b) {
    asm volatile("mma.sync.aligned.m16n8k16.row.col.f32.f16.f16.f32 "
        "{%0,%1,%2,%3}, {%4,%5,%6,%7}, {%8,%9}, {%0,%1,%2,%3};"
        : "+f"(c[0]), "+f"(c[1]), "+f"(c[2]), "+f"(c[3])
        : "r"(a[0]), "r"(a[1]), "r"(a[2]), "r"(a[3]), "r"(b[0]), "r"(b[1]));
}
#define LDMX4(r0, r1, r2, r3, addr) \
    asm volatile("ldmatrix.sync.aligned.m8n8.x4.shared.b16 {%0,%1,%2,%3}, [%4];" \
        : "=r"(r0), "=r"(r1), "=r"(r2), "=r"(r3) : "r"(addr))

static __device__ __forceinline__ void split2(float f0, float f1,
                                              uint32_t& hi, uint32_t& lo) {
    __half2 h = __floats2half2_rn(f0, f1);
    float2  fh = __half22float2(h);
    __half2 l = __floats2half2_rn(f0 - fh.x, f1 - fh.y);
    hi = *reinterpret_cast<uint32_t*>(&h);
    lo = *reinterpret_cast<uint32_t*>(&l);
}

// ---- pre-kernel: transpose W [K,N] -> [N,K], prescale, fp16-split, pack ----
__global__ void split_w_kernel(const float* __restrict__ W) {
    int idx = blockIdx.x * blockDim.x + threadIdx.x;   // over N*K/2
    if (idx < N_DIM * K_DIM / 2) {
        int n  = idx / (K_DIM / 2);
        int kk = idx - n * (K_DIM / 2);
        float w0 = W[(size_t)(2 * kk)     * N_DIM + n] * WSCALE;
        float w1 = W[(size_t)(2 * kk + 1) * N_DIM + n] * WSCALE;
        uint32_t hi, lo;
        split2(w0, w1, hi, lo);
        g_Wp_hi[idx] = hi;
        g_Wp_lo[idx] = lo;
    }
}

// ---- fused 3-pass fp16-split mma GEMM + softmax-stats + loss/acc ----
__global__ __launch_bounds__(NTHREADS, 2)
void fused_kernel(const float* __restrict__ x,
                  const float* __restrict__ bias,
                  const int* __restrict__ tags,
                  const float* __restrict__ t2s,
                  const int* __restrict__ tptr,
                  int M)
{
    extern __shared__ uint32_t smem[];
    float* smf = (float*)smem;
    const int tid  = threadIdx.x;
    const int w    = tid >> 5;    // warp 0..3
    const int lane = tid & 31;
    const int g    = lane >> 2;   // 0..7
    const int t    = lane & 3;    // 0..3
    const int m0   = blockIdx.x * BM;

    if (tid < N_DIM) smf[U_BIAS + tid] = bias[tid];

    const uint32_t smb = smem_u32(smem);
    const uint32_t buf_base[2] = { smb + U_BUF * 4u, smb + (U_BUF + U_BUFSZ) * 4u };

    // ldmatrix per-lane byte offsets (verified mapping from R7)
    uint32_t a_off[2];
    {
        const int r  = lane & 7;
        const int rb = (lane >> 3) & 1;
        const int kb = (lane >> 4) & 1;
        #pragma unroll
        for (int mt = 0; mt < 2; mt++) {
            int row = 32 * w + 16 * mt + 8 * rb + r;
            a_off[mt] = (U_XHI + row * STRIDE_U) * 4u + kb * 16u;
        }
    }
    uint32_t b_off[4];
    {
        const int r  = lane & 7;
        const int tl = lane >> 3;
        const int nb = tl >> 1;
        const int kb = tl & 1;
        #pragma unroll
        for (int p = 0; p < 4; p++) {
            int nrow = 16 * p + 8 * nb + r;
            b_off[p] = (U_WHI + nrow * STRIDE_U) * 4u + kb * 16u;
        }
    }
    const uint32_t XLO_D = (U_XLO - U_XHI) * 4u;
    const uint32_t WLO_D = (U_WLO - U_WHI) * 4u;

    // staging: thread tid stages x row tid (32 floats/chunk)
    int arow = m0 + tid; if (arow >= M) arow = M - 1;
    const float* xrow = x + (size_t)arow * K_DIM;
    // W staging: thread stages row wn = tid>>1, u32 cols wq..wq+7 (8 u32)
    const int wn = tid >> 1;
    const int wq = (tid & 1) * 8;
    const uint32_t* whp = g_Wp_hi + (size_t)wn * (K_DIM / 2) + wq;
    const uint32_t* wlp = g_Wp_lo + (size_t)wn * (K_DIM / 2) + wq;

    float acc[2][8][4];
    #pragma unroll
    for (int mt = 0; mt < 2; mt++)
        #pragma unroll
        for (int nt = 0; nt < 8; nt++)
            #pragma unroll
            for (int q = 0; q < 4; q++) acc[mt][nt][q] = 0.f;

    // prologue LDG chunk 0
    float4 xa[8]; uint4 wh[2], wl[2];
    #pragma unroll
    for (int q = 0; q < 8; q++) xa[q] = *(const float4*)(xrow + 4 * q);
    wh[0] = *(const uint4*)whp;       wh[1] = *(const uint4*)(whp + 4);
    wl[0] = *(const uint4*)wlp;       wl[1] = *(const uint4*)(wlp + 4);

    int buf = 0;
    for (int c = 0; c < NCHUNK; ++c) {
        uint32_t* S = smem + U_BUF + buf * U_BUFSZ;

        // ---- stage: fp16-split x; store pre-split W ----
        {
            uint32_t xh[16], xl[16];
            #pragma unroll
            for (int q = 0; q < 8; q++) {
                split2(xa[q].x, xa[q].y, xh[2 * q],     xl[2 * q]);
                split2(xa[q].z, xa[q].w, xh[2 * q + 1], xl[2 * q + 1]);
            }
            uint4* ph = (uint4*)(S + U_XHI + tid * STRIDE_U);
            uint4* pl = (uint4*)(S + U_XLO + tid * STRIDE_U);
            #pragma unroll
            for (int q = 0; q < 4; q++) {
                ph[q] = make_uint4(xh[4*q], xh[4*q+1], xh[4*q+2], xh[4*q+3]);
                pl[q] = make_uint4(xl[4*q], xl[4*q+1], xl[4*q+2], xl[4*q+3]);
            }
            uint4* pw = (uint4*)(S + U_WHI + wn * STRIDE_U + wq);
            uint4* qw = (uint4*)(S + U_WLO + wn * STRIDE_U + wq);
            pw[0] = wh[0]; pw[1] = wh[1];
            qw[0] = wl[0]; qw[1] = wl[1];
        }

        __syncthreads();

        // prefetch next chunk (window = 96 MMAs + 24 ldmatrix)
        if (c + 1 < NCHUNK) {
            const float* xp = xrow + (c + 1) * BK;
            #pragma unroll
            for (int q = 0; q < 8; q++) xa[q] = *(const float4*)(xp + 4 * q);
            const uint32_t* wph = whp + (c + 1) * (BK / 2);
            const uint32_t* wpl = wlp + (c + 1) * (BK / 2);
            wh[0] = *(const uint4*)wph;     wh[1] = *(const uint4*)(wph + 4);
            wl[0] = *(const uint4*)wpl;     wl[1] = *(const uint4*)(wpl + 4);
        }

        // ---- compute: 2 k16-steps, 48 MMAs each ----
        const uint32_t base = buf_base[buf];
        #pragma unroll
        for (int ks = 0; ks < 2; ks++) {
            const uint32_t kso = ks * 32u;
            uint32_t ah[2][4], al[2][4], bh[8][2], bl[8][2];
            #pragma unroll
            for (int mt = 0; mt < 2; mt++) {
                LDMX4(ah[mt][0], ah[mt][1], ah[mt][2], ah[mt][3], base + a_off[mt] + kso);
                LDMX4(al[mt][0], al[mt][1], al[mt][2], al[mt][3], base + a_off[mt] + kso + XLO_D);
            }
            #pragma unroll
            for (int p = 0; p < 4; p++) {
                LDMX4(bh[2*p][0], bh[2*p][1], bh[2*p+1][0], bh[2*p+1][1], base + b_off[p] + kso);
                LDMX4(bl[2*p][0], bl[2*p][1], bl[2*p+1][0], bl[2*p+1][1], base + b_off[p] + kso + WLO_D);
            }
            // term-major: same-accumulator MMAs 16 apart (no RAW stalls)
            #pragma unroll
            for (int nt = 0; nt < 8; nt++)
                #pragma unroll
                for (int mt = 0; mt < 2; mt++)
                    mma_f32acc(acc[mt][nt], ah[mt], bh[nt]);    // hi*hi
            #pragma unroll
            for (int nt = 0; nt < 8; nt++)
                #pragma unroll
                for (int mt = 0; mt < 2; mt++)
                    mma_f32acc(acc[mt][nt], ah[mt], bl[nt]);    // hi*lo
            #pragma unroll
            for (int nt = 0; nt < 8; nt++)
                #pragma unroll
                for (int mt = 0; mt < 2; mt++)
                    mma_f32acc(acc[mt][nt], al[mt], bh[nt]);    // lo*hi
        }
        buf ^= 1;
    }

    // ---- epilogue: quad owns rows; lane holds cols 8*nt + 2*t + j ----
    const int   tval = *tptr;
    const float E1   = 2.718281828459045f;
    float myLoss = 0.f;
    int myRight = 0, myCount = 0;

    #pragma unroll
    for (int mt = 0; mt < 2; mt++) {
        #pragma unroll
        for (int half = 0; half < 2; half++) {
            const int grow = m0 + 32 * w + 16 * mt + 8 * half + g;
            float v[16];
            float lmax = -1e30f, lsum = 0.f;
            int lidx = 0;
            #pragma unroll
            for (int nt = 0; nt < 8; nt++) {
                #pragma unroll
                for (int j = 0; j < 2; j++) {
                    const int col = 8 * nt + 2 * t + j;
                    float f = acc[mt][nt][2 * half + j] * INV_WSCALE + smf[U_BIAS + col];
                    v[2 * nt + j] = f;
                    lsum += f;
                    if (f > lmax) { lmax = f; lidx = col; }
                }
            }
            #pragma unroll
            for (int o = 1; o < 4; o <<= 1) {
                float om = __shfl_xor_sync(0xffffffffu, lmax, o, 4);
                int   oi = __shfl_xor_sync(0xffffffffu, lidx, o, 4);
                if (om > lmax || (om == lmax && oi < lidx)) { lmax = om; lidx = oi; }
            }
            float z = 0.f;
            #pragma unroll
            for (int q = 0; q < 16; q++) z += __expf(v[q] - lmax);
            #pragma unroll
            for (int o = 1; o < 4; o <<= 1) {
                z    += __shfl_xor_sync(0xffffffffu, z,    o, 4);
                lsum += __shfl_xor_sync(0xffffffffu, lsum, o, 4);
            }

            if (grow < M) {
                const int tg = tags[grow];
                if (((tg >> 1) & 3) == t) {
                    float ltag = v[0];
                    #pragma unroll
                    for (int nt = 0; nt < 8; nt++)
                        #pragma unroll
                        for (int j = 0; j < 2; j++)
                            if (tg == 8 * nt + 2 * t + j) ltag = v[2 * nt + j];

                    float logZ   = __logf(z);
                    float lp_tag = ltag - lmax - logZ;
                    float S_log  = lsum - 64.f * (lmax + logZ);
                    float s  = t2s[tg];
                    float sc = powf(s, (float)tval);
                    float es = __expf(sc);
                    float Zy = 63.f * E1 + es;
                    float y_non = E1 / Zy;
                    float y_hot = es / Zy;
                    myLoss -= y_non * S_log + (y_hot - y_non) * lp_tag;
                    if (tg < N_DIM - 3) { myCount++; if (lidx == tg) myRight++; }
                }
            }
        }
    }

    // ---- deterministic block tree-reduction ----
    __syncthreads();
    float* rl = smf + U_BUF;
    int*   rr = (int*)(smem + U_BUF + NTHREADS);
    int*   rc = (int*)(smem + U_BUF + 2 * NTHREADS);
    rl[tid] = myLoss; rr[tid] = myRight; rc[tid] = myCount;
    __syncthreads();
    #pragma unroll
    for (int s2 = NTHREADS / 2; s2 > 0; s2 >>= 1) {
        if (tid < s2) { rl[tid] += rl[tid + s2]; rr[tid] += rr[tid + s2]; rc[tid] += rc[tid + s2]; }
        __syncthreads();
    }
    if (tid == 0) {
        g_partLoss[blockIdx.x]  = rl[0];
        g_partRight[blockIdx.x] = rr[0];
        g_partCount[blockIdx.x] = rc[0];
    }
}

__global__ void finalize_kernel(float* __restrict__ out, int nb)
{
    __shared__ float sl[256];
    __shared__ int   sr[256];
    __shared__ int   sc[256];
    const int t = threadIdx.x;
    float L = 0.f; int R = 0, C = 0;
    for (int i = t; i < nb; i += 256) {
        L += g_partLoss[i]; R += g_partRight[i]; C += g_partCount[i];
    }
    sl[t] = L; sr[t] = R; sc[t] = C;
    __syncthreads();
    for (int s = 128; s > 0; s >>= 1) {
        if (t < s) { sl[t] += sl[t + s]; sr[t] += sr[t + s]; sc[t] += sc[t + s]; }
        __syncthreads();
    }
    if (t == 0) {
        out[0] = sl[0];
        out[1] = (float)sr[0] / (float)sc[0];
    }
}

extern "C" void kernel_launch(void* const* d_in, const int* in_sizes, int n_in,
                              void* d_out, int out_size)
{
    // metadata order: x, W, b, tags, attention_mask, tag_to_score, t
    const float* x    = (const float*)d_in[0];
    const float* W    = (const float*)d_in[1];
    const float* b    = (const float*)d_in[2];
    const int*   tags = (const int*)d_in[3];
    // d_in[4] attention_mask: uniform additive shift over softmax axis -> no-op
    const float* t2s  = (const float*)d_in[5];
    const int*   tptr = (const int*)d_in[6];

    const int M = in_sizes[3];                   // 32768
    int nblocks = (M + BM - 1) / BM;             // 256 -> single co-resident wave
    if (nblocks > MAX_BLOCKS) nblocks = MAX_BLOCKS;

    cudaFuncSetAttribute(fused_kernel, cudaFuncAttributeMaxDynamicSharedMemorySize, SMEM_BYTES);

    split_w_kernel<<<(N_DIM * K_DIM / 2 + 255) / 256, 256>>>(W);
    fused_kernel<<<nblocks, NTHREADS, SMEM_BYTES>>>(x, b, tags, t2s, tptr, M);
    finalize_kernel<<<1, 256>>>((float*)d_out, nblocks);
}

// round 9
// speedup vs baseline: 1.1868x; 1.0359x over previous
#include <cuda_runtime.h>
#include <cuda_fp16.h>
#include <cstdint>

// MlaNer1: B=64, L=512, H2=1536, T=64 -> GEMM M=32768, N=64, K=1536
#define K_DIM   1536
#define N_DIM   64
#define BM      128              // CTA M-tile (4 warps x 32 rows)
#define BK      32               // K per chunk = two k16 MMA steps
#define NCHUNK  (K_DIM / BK)     // 48
#define NTHREADS 128
#define MAX_BLOCKS 512
#define STRIDE_U 20              // u32 per row (16 data + 4 pad); 80B stride

// W prescale 2^10 (exact); logits descaled in epilogue
#define WSCALE     1024.0f
#define INV_WSCALE (1.0f / 1024.0f)

// smem u32-offsets
#define U_BIAS  0
#define U_BUF   64
#define U_XHI   0
#define U_XLO   (BM * STRIDE_U)                          // 2560
#define U_WHI   (2 * BM * STRIDE_U)                      // 5120
#define U_WLO   (2 * BM * STRIDE_U + N_DIM * STRIDE_U)   // 6400
#define U_BUFSZ (2 * BM * STRIDE_U + 2 * N_DIM * STRIDE_U) // 7680
#define SMEM_U32 (U_BUF + 2 * U_BUFSZ)                   // 15424
#define SMEM_BYTES (SMEM_U32 * 4)                        // 61696 (fits 2 CTA/SM)

__device__ float g_partLoss[MAX_BLOCKS];
__device__ int   g_partRight[MAX_BLOCKS];
__device__ int   g_partCount[MAX_BLOCKS];
// W transposed to [N,K], prescaled, fp16-split, packed half2
__device__ __align__(16) uint32_t g_Wp_hi[N_DIM * K_DIM / 2];
__device__ __align__(16) uint32_t g_Wp_lo[N_DIM * K_DIM / 2];

static __device__ __forceinline__ uint32_t smem_u32(const void* p) {
    uint32_t a;
    asm("{ .reg .u64 t; cvta.to.shared.u64 t, %1; cvt.u32.u64 %0, t; }" : "=r"(a) : "l"(p));
    return a;
}
// f32-acc fp16 MMA (hh term)
static __device__ __forceinline__ void mma_f32acc(float* c, const uint32_t* a,
                                                  const uint32_t* b) {
    asm volatile("mma.sync.aligned.m16n8k16.row.col.f32.f16.f16.f32 "
        "{%0,%1,%2,%3}, {%4,%5,%6,%7}, {%8,%9}, {%0,%1,%2,%3};"
        : "+f"(c[0]), "+f"(c[1]), "+f"(c[2]), "+f"(c[3])
        : "r"(a[0]), "r"(a[1]), "r"(a[2]), "r"(a[3]), "r"(b[0]), "r"(b[1]));
}
// f16-acc fp16 MMA (correction terms; tiny values -> fp16 acc safe, R7-verified)
static __device__ __forceinline__ void mma_f16acc(uint32_t* c, const uint32_t* a,
                                                  const uint32_t* b) {
    asm volatile("mma.sync.aligned.m16n8k16.row.col.f16.f16.f16.f16 "
        "{%0,%1}, {%2,%3,%4,%5}, {%6,%7}, {%0,%1};"
        : "+r"(c[0]), "+r"(c[1])
        : "r"(a[0]), "r"(a[1]), "r"(a[2]), "r"(a[3]), "r"(b[0]), "r"(b[1]));
}
#define LDMX4(r0, r1, r2, r3, addr) \
    asm volatile("ldmatrix.sync.aligned.m8n8.x4.shared.b16 {%0,%1,%2,%3}, [%4];" \
        : "=r"(r0), "=r"(r1), "=r"(r2), "=r"(r3) : "r"(addr))

static __device__ __forceinline__ void split2(float f0, float f1,
                                              uint32_t& hi, uint32_t& lo) {
    __half2 h = __floats2half2_rn(f0, f1);
    float2  fh = __half22float2(h);
    __half2 l = __floats2half2_rn(f0 - fh.x, f1 - fh.y);
    hi = *reinterpret_cast<uint32_t*>(&h);
    lo = *reinterpret_cast<uint32_t*>(&l);
}

// ---- pre-kernel: transpose W [K,N] -> [N,K], prescale, fp16-split, pack ----
__global__ void split_w_kernel(const float* __restrict__ W) {
    int idx = blockIdx.x * blockDim.x + threadIdx.x;   // over N*K/2
    if (idx < N_DIM * K_DIM / 2) {
        int n  = idx / (K_DIM / 2);
        int kk = idx - n * (K_DIM / 2);
        float w0 = W[(size_t)(2 * kk)     * N_DIM + n] * WSCALE;
        float w1 = W[(size_t)(2 * kk + 1) * N_DIM + n] * WSCALE;
        uint32_t hi, lo;
        split2(w0, w1, hi, lo);
        g_Wp_hi[idx] = hi;
        g_Wp_lo[idx] = lo;
    }
}

// ---- fused 3-pass fp16-split mma GEMM + softmax-stats + loss/acc ----
__global__ __launch_bounds__(NTHREADS, 2)
void fused_kernel(const float* __restrict__ x,
                  const float* __restrict__ bias,
                  const int* __restrict__ tags,
                  const float* __restrict__ t2s,
                  const int* __restrict__ tptr,
                  int M)
{
    extern __shared__ uint32_t smem[];
    float* smf = (float*)smem;
    const int tid  = threadIdx.x;
    const int w    = tid >> 5;    // warp 0..3
    const int lane = tid & 31;
    const int g    = lane >> 2;   // 0..7
    const int t    = lane & 3;    // 0..3
    const int m0   = blockIdx.x * BM;

    if (tid < N_DIM) smf[U_BIAS + tid] = bias[tid];

    const uint32_t smb = smem_u32(smem);
    const uint32_t buf_base[2] = { smb + U_BUF * 4u, smb + (U_BUF + U_BUFSZ) * 4u };

    // ldmatrix per-lane byte offsets (verified mapping)
    uint32_t a_off[2];
    {
        const int r  = lane & 7;
        const int rb = (lane >> 3) & 1;
        const int kb = (lane >> 4) & 1;
        #pragma unroll
        for (int mt = 0; mt < 2; mt++) {
            int row = 32 * w + 16 * mt + 8 * rb + r;
            a_off[mt] = (U_XHI + row * STRIDE_U) * 4u + kb * 16u;
        }
    }
    uint32_t b_off[4];
    {
        const int r  = lane & 7;
        const int tl = lane >> 3;
        const int nb = tl >> 1;
        const int kb = tl & 1;
        #pragma unroll
        for (int p = 0; p < 4; p++) {
            int nrow = 16 * p + 8 * nb + r;
            b_off[p] = (U_WHI + nrow * STRIDE_U) * 4u + kb * 16u;
        }
    }
    const uint32_t XLO_D = (U_XLO - U_XHI) * 4u;
    const uint32_t WLO_D = (U_WLO - U_WHI) * 4u;

    // staging: thread tid stages x row tid (32 floats/chunk)
    int arow = m0 + tid; if (arow >= M) arow = M - 1;
    const float* xrow = x + (size_t)arow * K_DIM;
    // W staging: thread stages row wn = tid>>1, u32 cols wq..wq+7
    const int wn = tid >> 1;
    const int wq = (tid & 1) * 8;
    const uint32_t* whp = g_Wp_hi + (size_t)wn * (K_DIM / 2) + wq;
    const uint32_t* wlp = g_Wp_lo + (size_t)wn * (K_DIM / 2) + wq;

    float    accF[2][8][4];     // hh (f32 acc)
    uint32_t accH[2][8][2];     // hl + lh (f16 acc)
    #pragma unroll
    for (int mt = 0; mt < 2; mt++)
        #pragma unroll
        for (int nt = 0; nt < 8; nt++) {
            #pragma unroll
            for (int q = 0; q < 4; q++) accF[mt][nt][q] = 0.f;
            accH[mt][nt][0] = 0u; accH[mt][nt][1] = 0u;
        }

    // prologue LDG chunk 0
    float4 xa[8]; uint4 wh[2], wl[2];
    #pragma unroll
    for (int q = 0; q < 8; q++) xa[q] = *(const float4*)(xrow + 4 * q);
    wh[0] = *(const uint4*)whp;       wh[1] = *(const uint4*)(whp + 4);
    wl[0] = *(const uint4*)wlp;       wl[1] = *(const uint4*)(wlp + 4);

    int buf = 0;
    for (int c = 0; c < NCHUNK; ++c) {
        uint32_t* S = smem + U_BUF + buf * U_BUFSZ;

        // ---- stage: fp16-split x; store pre-split W ----
        {
            uint32_t xh[16], xl[16];
            #pragma unroll
            for (int q = 0; q < 8; q++) {
                split2(xa[q].x, xa[q].y, xh[2 * q],     xl[2 * q]);
                split2(xa[q].z, xa[q].w, xh[2 * q + 1], xl[2 * q + 1]);
            }
            uint4* ph = (uint4*)(S + U_XHI + tid * STRIDE_U);
            uint4* pl = (uint4*)(S + U_XLO + tid * STRIDE_U);
            #pragma unroll
            for (int q = 0; q < 4; q++) {
                ph[q] = make_uint4(xh[4*q], xh[4*q+1], xh[4*q+2], xh[4*q+3]);
                pl[q] = make_uint4(xl[4*q], xl[4*q+1], xl[4*q+2], xl[4*q+3]);
            }
            uint4* pw = (uint4*)(S + U_WHI + wn * STRIDE_U + wq);
            uint4* qw = (uint4*)(S + U_WLO + wn * STRIDE_U + wq);
            pw[0] = wh[0]; pw[1] = wh[1];
            qw[0] = wl[0]; qw[1] = wl[1];
        }

        __syncthreads();

        // prefetch next chunk
        if (c + 1 < NCHUNK) {
            const float* xp = xrow + (c + 1) * BK;
            #pragma unroll
            for (int q = 0; q < 8; q++) xa[q] = *(const float4*)(xp + 4 * q);
            const uint32_t* wph = whp + (c + 1) * (BK / 2);
            const uint32_t* wpl = wlp + (c + 1) * (BK / 2);
            wh[0] = *(const uint4*)wph;     wh[1] = *(const uint4*)(wph + 4);
            wl[0] = *(const uint4*)wpl;     wl[1] = *(const uint4*)(wpl + 4);
        }

        // ---- compute: 2 k16-steps; hh f32-acc, corrections f16-acc ----
        const uint32_t base = buf_base[buf];
        #pragma unroll
        for (int ks = 0; ks < 2; ks++) {
            const uint32_t kso = ks * 32u;
            uint32_t ah[2][4], al[2][4], bh[8][2], bl[8][2];
            #pragma unroll
            for (int mt = 0; mt < 2; mt++) {
                LDMX4(ah[mt][0], ah[mt][1], ah[mt][2], ah[mt][3], base + a_off[mt] + kso);
                LDMX4(al[mt][0], al[mt][1], al[mt][2], al[mt][3], base + a_off[mt] + kso + XLO_D);
            }
            #pragma unroll
            for (int p = 0; p < 4; p++) {
                LDMX4(bh[2*p][0], bh[2*p][1], bh[2*p+1][0], bh[2*p+1][1], base + b_off[p] + kso);
                LDMX4(bl[2*p][0], bl[2*p][1], bl[2*p+1][0], bl[2*p+1][1], base + b_off[p] + kso + WLO_D);
            }
            #pragma unroll
            for (int nt = 0; nt < 8; nt++)
                #pragma unroll
                for (int mt = 0; mt < 2; mt++)
                    mma_f32acc(accF[mt][nt], ah[mt], bh[nt]);   // hi*hi
            #pragma unroll
            for (int nt = 0; nt < 8; nt++)
                #pragma unroll
                for (int mt = 0; mt < 2; mt++)
                    mma_f16acc(accH[mt][nt], ah[mt], bl[nt]);   // hi*lo
            #pragma unroll
            for (int nt = 0; nt < 8; nt++)
                #pragma unroll
                for (int mt = 0; mt < 2; mt++)
                    mma_f16acc(accH[mt][nt], al[mt], bh[nt]);   // lo*hi
        }
        buf ^= 1;
    }

    // ---- epilogue: quad owns rows; lane holds cols 8*nt + 2*t + j ----
    const int   tval = *tptr;
    const float E1   = 2.718281828459045f;
    float myLoss = 0.f;
    int myRight = 0, myCount = 0;

    #pragma unroll
    for (int mt = 0; mt < 2; mt++) {
        #pragma unroll
        for (int half = 0; half < 2; half++) {
            const int grow = m0 + 32 * w + 16 * mt + 8 * half + g;
            float v[16];
            float lmax = -1e30f, lsum = 0.f;
            int lidx = 0;
            #pragma unroll
            for (int nt = 0; nt < 8; nt++) {
                __half2 hc = *reinterpret_cast<__half2*>(&accH[mt][nt][half]);
                float2  cf = __half22float2(hc);
                #pragma unroll
                for (int j = 0; j < 2; j++) {
                    const int col = 8 * nt + 2 * t + j;
                    float corr = j ? cf.y : cf.x;
                    float f = (accF[mt][nt][2 * half + j] + corr) * INV_WSCALE
                              + smf[U_BIAS + col];
                    v[2 * nt + j] = f;
                    lsum += f;
                    if (f > lmax) { lmax = f; lidx = col; }
                }
            }
            #pragma unroll
            for (int o = 1; o < 4; o <<= 1) {
                float om = __shfl_xor_sync(0xffffffffu, lmax, o, 4);
                int   oi = __shfl_xor_sync(0xffffffffu, lidx, o, 4);
                if (om > lmax || (om == lmax && oi < lidx)) { lmax = om; lidx = oi; }
            }
            float z = 0.f;
            #pragma unroll
            for (int q = 0; q < 16; q++) z += __expf(v[q] - lmax);
            #pragma unroll
            for (int o = 1; o < 4; o <<= 1) {
                z    += __shfl_xor_sync(0xffffffffu, z,    o, 4);
                lsum += __shfl_xor_sync(0xffffffffu, lsum, o, 4);
            }

            if (grow < M) {
                const int tg = tags[grow];
                if (((tg >> 1) & 3) == t) {
                    float ltag = v[0];
                    #pragma unroll
                    for (int nt = 0; nt < 8; nt++)
                        #pragma unroll
                        for (int j = 0; j < 2; j++)
                            if (tg == 8 * nt + 2 * t + j) ltag = v[2 * nt + j];

                    float logZ   = __logf(z);
                    float lp_tag = ltag - lmax - logZ;
                    float S_log  = lsum - 64.f * (lmax + logZ);
                    float s  = t2s[tg];
                    float sc = powf(s, (float)tval);
                    float es = __expf(sc);
                    float Zy = 63.f * E1 + es;
                    float y_non = E1 / Zy;
                    float y_hot = es / Zy;
                    myLoss -= y_non * S_log + (y_hot - y_non) * lp_tag;
                    if (tg < N_DIM - 3) { myCount++; if (lidx == tg) myRight++; }
                }
            }
        }
    }

    // ---- deterministic block tree-reduction ----
    __syncthreads();
    float* rl = smf + U_BUF;
    int*   rr = (int*)(smem + U_BUF + NTHREADS);
    int*   rc = (int*)(smem + U_BUF + 2 * NTHREADS);
    rl[tid] = myLoss; rr[tid] = myRight; rc[tid] = myCount;
    __syncthreads();
    #pragma unroll
    for (int s2 = NTHREADS / 2; s2 > 0; s2 >>= 1) {
        if (tid < s2) { rl[tid] += rl[tid + s2]; rr[tid] += rr[tid + s2]; rc[tid] += rc[tid + s2]; }
        __syncthreads();
    }
    if (tid == 0) {
        g_partLoss[blockIdx.x]  = rl[0];
        g_partRight[blockIdx.x] = rr[0];
        g_partCount[blockIdx.x] = rc[0];
    }
}

__global__ void finalize_kernel(float* __restrict__ out, int nb)
{
    __shared__ float sl[256];
    __shared__ int   sr[256];
    __shared__ int   sc[256];
    const int t = threadIdx.x;
    float L = 0.f; int R = 0, C = 0;
    for (int i = t; i < nb; i += 256) {
        L += g_partLoss[i]; R += g_partRight[i]; C += g_partCount[i];
    }
    sl[t] = L; sr[t] = R; sc[t] = C;
    __syncthreads();
    for (int s = 128; s > 0; s >>= 1) {
        if (t < s) { sl[t] += sl[t + s]; sr[t] += sr[t + s]; sc[t] += sc[t + s]; }
        __syncthreads();
    }
    if (t == 0) {
        out[0] = sl[0];
        out[1] = (float)sr[0] / (float)sc[0];
    }
}

extern "C" void kernel_launch(void* const* d_in, const int* in_sizes, int n_in,
                              void* d_out, int out_size)
{
    // metadata order: x, W, b, tags, attention_mask, tag_to_score, t
    const float* x    = (const float*)d_in[0];
    const float* W    = (const float*)d_in[1];
    const float* b    = (const float*)d_in[2];
    const int*   tags = (const int*)d_in[3];
    // d_in[4] attention_mask: uniform additive shift over softmax axis -> no-op
    const float* t2s  = (const float*)d_in[5];
    const int*   tptr = (const int*)d_in[6];

    const int M = in_sizes[3];                   // 32768
    int nblocks = (M + BM - 1) / BM;             // 256 -> single co-resident wave
    if (nblocks > MAX_BLOCKS) nblocks = MAX_BLOCKS;

    cudaFuncSetAttribute(fused_kernel, cudaFuncAttributeMaxDynamicSharedMemorySize, SMEM_BYTES);

    split_w_kernel<<<(N_DIM * K_DIM / 2 + 255) / 256, 256>>>(W);
    fused_kernel<<<nblocks, NTHREADS, SMEM_BYTES>>>(x, b, tags, t2s, tptr, M);
    finalize_kernel<<<1, 256>>>((float*)d_out, nblocks);
}